// round 10
// baseline (speedup 1.0000x reference)
#include <cuda_runtime.h>

// Fixed problem shape
#define BB 256
#define TT 4096
#define CC 16
#define HH 20
#define GG 60
#define K  16
#define NC (TT / K)   // 256 chunks

typedef unsigned long long u64;

__device__ __forceinline__ u64 pack2(float a, float b) {
    u64 r; asm("mov.b64 %0,{%1,%2};" : "=l"(r) : "f"(a), "f"(b)); return r;
}
__device__ __forceinline__ void unpack2(u64 v, float& a, float& b) {
    asm("mov.b64 {%0,%1},%2;" : "=f"(a), "=f"(b) : "l"(v));
}
__device__ __forceinline__ void fma2(u64& d, u64 a, u64 b) {
    asm("fma.rn.f32x2 %0,%1,%2,%0;" : "+l"(d) : "l"(a), "l"(b));
}
__device__ __forceinline__ float hsum2(u64 v) {
    float x, y; unpack2(v, x, y); return x + y;
}
__device__ __forceinline__ float tanha(float x) {
    float y; asm("tanh.approx.f32 %0,%1;" : "=f"(y) : "f"(x)); return y;
}

// ---------------------------------------------------------------------------
// Single fused kernel. 2 batches per block, 8 warps, 128 blocks (1/SM).
// Warp map (SMSP = w%4; latency-critical chain warps at HIGH wid):
//   w0=GX0+xDMA+head(A) S0   w1=GX1(A) S1   w2=GX0+..(B) S2   w3=GX1(B) S3
//   w4=L0(A)            S0   w5=L1(A)  S1   w6=L0(B)     S2   w7=L1(B)  S3
// Stage lags: GX0 chunk c, L0 c-1, GX1 c-2, L1 c-3, head c-4. Rings 2-deep.
// gx (r,z) rows are stored PACKED as u64 (prescaled by 0.5); the chain folds
// them into the dot-accumulator init pack2(gx_r, bias_r) so hsum2 absorbs the
// add. h rows are exchanged via STS.32 + in-order LSU + LDS.128 (no syncwarp).
// sigmoid(s) = fma(tanh.approx(prescaled_sum), 0.5, 0.5).
// ---------------------------------------------------------------------------
__global__ void __launch_bounds__(256, 1)
fused_gru_kernel(const float* __restrict__ x,      // [B,T,C]
                 const float* __restrict__ h0in,   // [B,2,H]
                 const float* __restrict__ W_ih0, const float* __restrict__ W_hh0,
                 const float* __restrict__ b_ih0, const float* __restrict__ b_hh0,
                 const float* __restrict__ W_ih1, const float* __restrict__ W_hh1,
                 const float* __restrict__ b_ih1, const float* __restrict__ b_hh1,
                 const float* __restrict__ W_o,   const float* __restrict__ b_o,
                 float* __restrict__ out)          // o[B*T] then h_n[B,2,H]
{
    __shared__ __align__(16) u64   s_rz0[2][2][K][HH];  // packed (r,z) of gx0, 10 KB
    __shared__ __align__(16) float s_n0 [2][2][K][HH];  // n of gx0, 5 KB
    __shared__ __align__(16) u64   s_rz1[2][2][K][HH];  // packed (r,z) of gx1, 10 KB
    __shared__ __align__(16) float s_n1 [2][2][K][HH];  // 5 KB
    __shared__ __align__(16) float s_h0 [2][2][K][HH];  // 5 KB
    __shared__ __align__(16) float s_h1 [2][2][K][HH];  // 5 KB
    __shared__ __align__(16) float s_x  [2][2][K][CC];  // 4 KB

    const int tid = threadIdx.x;
    const int w   = tid >> 5;
    const int i   = tid & 31;
    const bool act = (i < HH);
    const int  ii  = act ? i : 0;          // clamped index for smem reads
    const unsigned FULL = 0xFFFFFFFFu;

    const bool low  = (w < 4);
    const int bs    = low ? (w >> 1) : ((w - 4) >> 1);
    const int kind  = w & 1;               // low: 0=GX0+head 1=GX1 ; high: 0=L0 1=L1
    const int b     = blockIdx.x * 2 + bs;
    const float* xb = x + (size_t)b * TT * CC;

    // ---- prime x chunk 0 (GX0 warps): 256 floats = 64 float4 ---------------
    if (low && kind == 0) {
        const float4* src = (const float4*)xb;
        float4* dst = (float4*)&s_x[bs][0][0][0];
        dst[i] = src[i]; dst[i + 32] = src[i + 32];
    }
    __syncthreads();

    if (low && kind == 0) {
        // ============ GX0 + x DMA + output head ==============================
        u64 wp[24];
        u64 wo2[10];
        float br = 0.f, bz = 0.f, bn = 0.f;
#pragma unroll
        for (int g = 0; g < 3; ++g) {
            const float sc = (g < 2) ? 0.5f : 1.0f;
#pragma unroll
            for (int k = 0; k < 8; ++k)
                wp[g * 8 + k] = act ? pack2(sc * W_ih0[(g * HH + i) * CC + 2 * k],
                                            sc * W_ih0[(g * HH + i) * CC + 2 * k + 1])
                                    : pack2(0.f, 0.f);
        }
#pragma unroll
        for (int k = 0; k < 10; ++k)
            wo2[k] = pack2(W_o[2 * k], W_o[2 * k + 1]);
        if (act) { br = 0.5f * b_ih0[i]; bz = 0.5f * b_ih0[HH + i]; bn = b_ih0[2 * HH + i]; }
        const float bo = b_o[0];
        float* ob = out + (size_t)b * TT;

        for (int c = 0; c < NC + 5; ++c) {
            float4 pf0, pf1;
            const bool pf = (c + 1 < NC);
            if (pf) {
                const float4* src = (const float4*)(xb + (size_t)(c + 1) * K * CC);
                pf0 = src[i]; pf1 = src[i + 32];
            }
            if (c < NC) {
                const float* xs = &s_x[bs][c & 1][0][0];
                u64*   rzo = &s_rz0[bs][c & 1][0][0];
                float* no_ = &s_n0 [bs][c & 1][0][0];
#pragma unroll 4
                for (int s = 0; s < K; ++s) {
                    const ulonglong2* xv2 = (const ulonglong2*)(xs + s * CC);
                    ulonglong2 xq0 = xv2[0], xq1 = xv2[1], xq2 = xv2[2], xq3 = xv2[3];
                    u64 xq[8] = {xq0.x, xq0.y, xq1.x, xq1.y, xq2.x, xq2.y, xq3.x, xq3.y};
                    u64 ar = pack2(br, 0.f), az = pack2(bz, 0.f), an = pack2(bn, 0.f);
#pragma unroll
                    for (int k = 0; k < 8; ++k) {
                        fma2(ar, wp[k],      xq[k]);
                        fma2(az, wp[8 + k],  xq[k]);
                        fma2(an, wp[16 + k], xq[k]);
                    }
                    if (act) {
                        rzo[s * HH + i] = pack2(hsum2(ar), hsum2(az));
                        no_[s * HH + i] = hsum2(an);
                    }
                }
            }
            // output head for chunk c-4: lane l<K computes step l's dot
            const int ch = c - 4;
            if (ch >= 0 && ch < NC && i < K) {
                const ulonglong2* hv2 = (const ulonglong2*)&s_h1[bs][ch & 1][i][0];
                ulonglong2 p0 = hv2[0], p1 = hv2[1], p2 = hv2[2], p3 = hv2[3], p4 = hv2[4];
                u64 hq[10] = {p0.x, p0.y, p1.x, p1.y, p2.x, p2.y, p3.x, p3.y, p4.x, p4.y};
                u64 acc = pack2(bo, 0.f);
#pragma unroll
                for (int k = 0; k < 10; ++k) fma2(acc, wo2[k], hq[k]);
                ob[ch * K + i] = hsum2(acc);
            }
            if (pf) {
                float4* dst = (float4*)&s_x[bs][(c + 1) & 1][0][0];
                dst[i] = pf0; dst[i + 32] = pf1;
            }
            __syncthreads();
        }
    } else if (low) {
        // ============ GX1: gx1 = W_ih1 . h0 (rz prescaled+packed) ============
        u64 wi[30];
        float br = 0.f, bz = 0.f, bn = 0.f;
#pragma unroll
        for (int g = 0; g < 3; ++g) {
            const float sc = (g < 2) ? 0.5f : 1.0f;
#pragma unroll
            for (int k = 0; k < 10; ++k)
                wi[g * 10 + k] = act ? pack2(sc * W_ih1[(g * HH + i) * HH + 2 * k],
                                             sc * W_ih1[(g * HH + i) * HH + 2 * k + 1])
                                     : pack2(0.f, 0.f);
        }
        if (act) { br = 0.5f * b_ih1[i]; bz = 0.5f * b_ih1[HH + i]; bn = b_ih1[2 * HH + i]; }

        for (int c = 0; c < NC + 5; ++c) {
            const int cg = c - 2;
            if (cg >= 0 && cg < NC) {
                const float* hr = &s_h0[bs][cg & 1][0][0];
                u64*   rzo = &s_rz1[bs][cg & 1][0][0];
                float* no_ = &s_n1 [bs][cg & 1][0][0];
#pragma unroll 4
                for (int s = 0; s < K; ++s) {
                    const ulonglong2* hv2 = (const ulonglong2*)(hr + s * HH);
                    ulonglong2 p0 = hv2[0], p1 = hv2[1], p2 = hv2[2], p3 = hv2[3], p4 = hv2[4];
                    u64 hq[10] = {p0.x, p0.y, p1.x, p1.y, p2.x, p2.y, p3.x, p3.y, p4.x, p4.y};
                    u64 qr = pack2(br, 0.f), qz = pack2(bz, 0.f), qn = pack2(bn, 0.f);
#pragma unroll
                    for (int k = 0; k < 10; ++k) {
                        fma2(qr, wi[k],      hq[k]);
                        fma2(qz, wi[10 + k], hq[k]);
                        fma2(qn, wi[20 + k], hq[k]);
                    }
                    if (act) {
                        rzo[s * HH + i] = pack2(hsum2(qr), hsum2(qz));
                        no_[s * HH + i] = hsum2(qn);
                    }
                }
            }
            __syncthreads();
        }
    } else {
        // ============ L0 / L1: pure recurrence chains ========================
        const bool isL0  = (kind == 0);
        const float* Whh = isL0 ? W_hh0 : W_hh1;
        const float* bhh = isL0 ? b_hh0 : b_hh1;
        const int lag    = isL0 ? 1 : 3;
        const int layer  = isL0 ? 0 : 1;

        u64 wh[30];
        float br = 0.f, bz = 0.f, bn = 0.f, h = 0.f;
#pragma unroll
        for (int g = 0; g < 3; ++g) {
            const float sc = (g < 2) ? 0.5f : 1.0f;
#pragma unroll
            for (int k = 0; k < 10; ++k)
                wh[g * 10 + k] = act ? pack2(sc * Whh[(g * HH + i) * HH + 2 * k],
                                             sc * Whh[(g * HH + i) * HH + 2 * k + 1])
                                     : pack2(0.f, 0.f);
        }
        if (act) {
            br = 0.5f * bhh[i]; bz = 0.5f * bhh[HH + i]; bn = bhh[2 * HH + i];
            h = h0in[(b * 2 + layer) * HH + i];
        }

        // initial broadcast of h (once)
        u64 hp[10];
#pragma unroll
        for (int k = 0; k < 10; ++k)
            hp[k] = pack2(__shfl_sync(FULL, h, 2 * k),
                          __shfl_sync(FULL, h, 2 * k + 1));

        for (int c = 0; c < NC + 5; ++c) {
            const int cc = c - lag;
            if (cc >= 0 && cc < NC) {
                const u64*   rz = isL0 ? &s_rz0[bs][cc & 1][0][0] : &s_rz1[bs][cc & 1][0][0];
                const float* nn_= isL0 ? &s_n0 [bs][cc & 1][0][0] : &s_n1 [bs][cc & 1][0][0];
                float* hw = isL0 ? &s_h0[bs][cc & 1][0][0] : &s_h1[bs][cc & 1][0][0];
#pragma unroll 2
                for (int s = 0; s < K; ++s) {
                    // gx for this step (prescaled; packed r,z)
                    const u64 grz = rz[s * HH + ii];
                    const float gn = nn_[s * HH + ii];
                    float gr, gz; unpack2(grz, gr, gz);
                    // accumulator init folds gx + bias: hsum2 absorbs the add
                    u64 ar = pack2(br, gr);
#pragma unroll
                    for (int k = 0; k < 10; ++k) fma2(ar, wh[k], hp[k]);
                    u64 az = pack2(bz, gz);
#pragma unroll
                    for (int k = 0; k < 10; ++k) fma2(az, wh[10 + k], hp[k]);
                    u64 an = pack2(bn, 0.f);
#pragma unroll
                    for (int k = 0; k < 10; ++k) fma2(an, wh[20 + k], hp[k]);

                    const float r = fmaf(tanha(hsum2(ar)), 0.5f, 0.5f);
                    const float z = fmaf(tanha(hsum2(az)), 0.5f, 0.5f);
                    const float n = tanha(fmaf(r, hsum2(an), gn));
                    h = fmaf(z, h - n, n);

                    // exchange h through the s_h row. Same-warp STS -> LDS is
                    // processed in order by the LSU; compiler barrier prevents
                    // reordering. (Also feeds GX1/head warps across the
                    // chunk-boundary __syncthreads.)
                    if (act) hw[s * HH + i] = h;
                    asm volatile("" ::: "memory");
                    const ulonglong2* hv2 = (const ulonglong2*)(hw + s * HH);
                    ulonglong2 p0 = hv2[0], p1 = hv2[1], p2 = hv2[2], p3 = hv2[3], p4 = hv2[4];
                    hp[0] = p0.x; hp[1] = p0.y; hp[2] = p1.x; hp[3] = p1.y;
                    hp[4] = p2.x; hp[5] = p2.y; hp[6] = p3.x; hp[7] = p3.y;
                    hp[8] = p4.x; hp[9] = p4.y;
                }
            }
            __syncthreads();
        }
        if (act) out[(size_t)BB * TT + (b * 2 + layer) * HH + i] = h;
    }
}

// ---------------------------------------------------------------------------
extern "C" void kernel_launch(void* const* d_in, const int* in_sizes, int n_in,
                              void* d_out, int out_size) {
    const float* x     = (const float*)d_in[0];
    const float* h0    = (const float*)d_in[1];
    const float* W_ih0 = (const float*)d_in[2];
    const float* W_hh0 = (const float*)d_in[3];
    const float* b_ih0 = (const float*)d_in[4];
    const float* b_hh0 = (const float*)d_in[5];
    const float* W_ih1 = (const float*)d_in[6];
    const float* W_hh1 = (const float*)d_in[7];
    const float* b_ih1 = (const float*)d_in[8];
    const float* b_hh1 = (const float*)d_in[9];
    const float* W_o   = (const float*)d_in[10];
    const float* b_o   = (const float*)d_in[11];

    fused_gru_kernel<<<BB / 2, 256>>>(x, h0, W_ih0, W_hh0, b_ih0, b_hh0,
                                      W_ih1, W_hh1, b_ih1, b_hh1, W_o, b_o,
                                      (float*)d_out);
}